// round 10
// baseline (speedup 1.0000x reference)
#include <cuda_runtime.h>
#include <cuda_bf16.h>
#include <math.h>
#include <stdint.h>

// Problem constants
#define SEQ     1024
#define BATCH   2
#define TOK     (SEQ*BATCH)   // 2048 tokens
#define HID     1024
#define NHEADS  16
#define HDIM    64
#define INTER   2730
#define INTERP  2736          // INTER padded to %16 (=171*16) for vector loads
#define NLAYERS 6
#define VOCAB   32000
#define QKV3    (3*HID)       // 3072
#define LN_EPS  1e-5f
#define ATT_SCALE 0.125f      // 1/sqrt(64)

// MMA GEMM smem geometry: k-slab 16, row pad 136 floats.
// Mainloop frag reads: bank = (8*t + g + c) % 32 -> exact 0..31 cover, conflict-free.
#define KSLAB 16
#define GPAD  136
#define GTILE (KSLAB*GPAD)                       // floats per array per stage
#define GSMEM_BYTES (2*4*GTILE*sizeof(float))    // 2 stages x {AsH,AsL,BsH,BsL} = 68KB

// ---------------------------------------------------------------------------
// Scratch (static __device__ globals: allocation-guard safe, zero-initialized
// at module load — the INTERP padding columns are never written and stay 0).
// ---------------------------------------------------------------------------
__device__ float g_h[TOK*HID];
__device__ float g_x[TOK*HID];
__device__ float g_qkv[TOK*QKV3];
__device__ float g_scores[(size_t)BATCH*NHEADS*SEQ*SEQ];
__device__ float g_ctx[TOK*HID];
__device__ float g_gate[(size_t)TOK*INTERP];
__device__ float g_up[(size_t)TOK*INTERP];

// ---------------------------------------------------------------------------
// Block reductions
// ---------------------------------------------------------------------------
__device__ __forceinline__ float block_sum(float v) {
    __shared__ float red[32];
    int lane = threadIdx.x & 31, w = threadIdx.x >> 5;
    __syncthreads();
    #pragma unroll
    for (int o = 16; o > 0; o >>= 1) v += __shfl_down_sync(0xffffffffu, v, o);
    if (lane == 0) red[w] = v;
    __syncthreads();
    int nw = blockDim.x >> 5;
    float r = (threadIdx.x < nw) ? red[threadIdx.x] : 0.f;
    if (w == 0) {
        #pragma unroll
        for (int o = 16; o > 0; o >>= 1) r += __shfl_down_sync(0xffffffffu, r, o);
        if (lane == 0) red[0] = r;
    }
    __syncthreads();
    return red[0];
}

__device__ __forceinline__ float block_max(float v) {
    __shared__ float red[32];
    int lane = threadIdx.x & 31, w = threadIdx.x >> 5;
    __syncthreads();
    #pragma unroll
    for (int o = 16; o > 0; o >>= 1) v = fmaxf(v, __shfl_down_sync(0xffffffffu, v, o));
    if (lane == 0) red[w] = v;
    __syncthreads();
    int nw = blockDim.x >> 5;
    float r = (threadIdx.x < nw) ? red[threadIdx.x] : -1e30f;
    if (w == 0) {
        #pragma unroll
        for (int o = 16; o > 0; o >>= 1) r = fmaxf(r, __shfl_down_sync(0xffffffffu, r, o));
        if (lane == 0) red[0] = r;
    }
    __syncthreads();
    return red[0];
}

// ---------------------------------------------------------------------------
// tf32 helpers
// ---------------------------------------------------------------------------
__device__ __forceinline__ uint32_t f2tf32(float x) {
    uint32_t r;
    asm("cvt.rna.tf32.f32 %0, %1;" : "=r"(r) : "f"(x));
    return r;
}

__device__ __forceinline__ void mma_tf32(float c[4], const uint32_t a[4], const uint32_t b[2]) {
    asm volatile(
        "mma.sync.aligned.m16n8k8.row.col.f32.tf32.tf32.f32 "
        "{%0,%1,%2,%3}, {%4,%5,%6,%7}, {%8,%9}, {%0,%1,%2,%3};"
        : "+f"(c[0]), "+f"(c[1]), "+f"(c[2]), "+f"(c[3])
        : "r"(a[0]), "r"(a[1]), "r"(a[2]), "r"(a[3]), "r"(b[0]), "r"(b[1]));
}

// ---------------------------------------------------------------------------
// Embedding
// ---------------------------------------------------------------------------
__global__ void embed_kernel(const int* __restrict__ ids, const float* __restrict__ tok,
                             const float* __restrict__ pos, float* __restrict__ h) {
    int t = blockIdx.x;
    int s = t % SEQ;
    int id = ids[t];
    const float* te = tok + (size_t)id * HID;
    const float* pe = pos + (size_t)s * HID;
    float* hp = h + (size_t)t * HID;
    for (int i = threadIdx.x; i < HID; i += blockDim.x) hp[i] = te[i] + pe[i];
}

// ---------------------------------------------------------------------------
// LayerNorm
// ---------------------------------------------------------------------------
__global__ void ln_kernel(const float* __restrict__ in, const float* __restrict__ w,
                          const float* __restrict__ bb, float* __restrict__ out) {
    __shared__ float row[HID];
    int t = blockIdx.x;
    const float* xp = in + (size_t)t * HID;
    float s = 0.f;
    for (int i = threadIdx.x; i < HID; i += blockDim.x) { float v = xp[i]; row[i] = v; s += v; }
    s = block_sum(s);
    float mu = s * (1.f / HID);
    float s2 = 0.f;
    for (int i = threadIdx.x; i < HID; i += blockDim.x) { float d = row[i] - mu; s2 += d * d; }
    s2 = block_sum(s2);
    float rstd = rsqrtf(s2 * (1.f / HID) + LN_EPS);
    float* op = out + (size_t)t * HID;
    for (int i = threadIdx.x; i < HID; i += blockDim.x)
        op[i] = (row[i] - mu) * rstd * w[i] + bb[i];
}

// ---------------------------------------------------------------------------
// Unified tensor-core GEMM (3xTF32):
//   C[m,n] = scale * sum_{k<Kb} A[m*lda + k] * B[n*ldbN + k*ldbK]  (+ EPI)
// K = k-loop extent (%KSLAB for VEC>=1 A); Kb = real reduction depth used for
// scalar-path guards. When K > Kb (padded-A case) A's padding MUST be zeros.
// Batched via blockIdx.z: operand offsets (z>>4)*so + (z&15)*si.
// Block tile 128 x (16*NF), 256 threads = 8 warps (4m x 2n),
// warp tile 32 x (8*NF). NF=8 -> 128-wide tile, NF=4 -> 64-wide tile.
// mma.m16n8k8.tf32, hi/lo split at smem-store time, double-buffered.
// EPI: 0 = C = scale*acc, 1 = C += acc, 2 = C = silu(acc) * U
// VEC: 0 = scalar loads, 1 = float4 A only (B scalar), 2 = float4 A and B.
//      VEC>=1 requires K%16==0 and 16B-aligned A rows; VEC==2 additionally
//      ldbK==1, 16B-aligned B rows, and K==Kb. N must be even.
//
// Fragment layouts (lane = g*4+t):
//   A: a0=(g,t) a1=(g+8,t) a2=(g,t+4) a3=(g+8,t+4)   [m, k]
//   B: b0=(t,g) b1=(t+4,g)                            [k, n]
//   C: c0=(g,2t) c1=(g,2t+1) c2=(g+8,2t) c3=(g+8,2t+1)
// ---------------------------------------------------------------------------
template<int EPI, int VEC, int NF>
__global__ __launch_bounds__(256)
void gemm_mma(const float* __restrict__ A, const float* __restrict__ B,
              float* __restrict__ C, const float* __restrict__ U,
              int M, int N, int K, int Kb,
              int lda, int ldbN, int ldbK, int ldc,
              size_t sAo, size_t sAi, size_t sBo, size_t sBi,
              size_t sCo, size_t sCi, float scale) {
    extern __shared__ float smem[];
    const unsigned z = blockIdx.z;
    A += (size_t)(z >> 4) * sAo + (size_t)(z & 15) * sAi;
    B += (size_t)(z >> 4) * sBo + (size_t)(z & 15) * sBi;
    C += (size_t)(z >> 4) * sCo + (size_t)(z & 15) * sCi;

    const int bm = blockIdx.y * 128, bn = blockIdx.x * (16 * NF);
    const int tid = threadIdx.x;
    const int wid = tid >> 5, lane = tid & 31;
    const int g = lane >> 2, t = lane & 3;
    const int wm = (wid >> 1) * 32;         // warp row offset (0,32,64,96)
    const int wn = (wid & 1) * (8 * NF);    // warp col offset

    // loaders: 256 threads cover 128 rows x 16 k
    const int lr = tid >> 1;            // 0..127
    const int lk = (tid & 1) * 8;       // 0 or 8

    float acc[2][NF][4];
    #pragma unroll
    for (int mf = 0; mf < 2; mf++)
        #pragma unroll
        for (int nf = 0; nf < NF; nf++)
            #pragma unroll
            for (int r = 0; r < 4; r++) acc[mf][nf][r] = 0.f;

    const int arow = bm + lr;
    const int brow = bn + lr;
    const bool aok = arow < M, bok = brow < N;
    const float* Ap = A + (size_t)arow * lda + lk;              // A k-stride always 1
    const float* Bp = B + (size_t)brow * ldbN + (size_t)lk * ldbK;

    float ra[8], rb[8];

    // ---- load helpers (compile-time dispatch) ----
    auto loadA = [&](int kbase) {
        if (VEC >= 1) {
            float4 v0, v1;
            if (aok) {
                v0 = *(const float4*)(Ap + kbase);
                v1 = *(const float4*)(Ap + kbase + 4);
            } else {
                v0 = make_float4(0.f, 0.f, 0.f, 0.f);
                v1 = v0;
            }
            ra[0] = v0.x; ra[1] = v0.y; ra[2] = v0.z; ra[3] = v0.w;
            ra[4] = v1.x; ra[5] = v1.y; ra[6] = v1.z; ra[7] = v1.w;
        } else {
            #pragma unroll
            for (int i = 0; i < 8; i++) {
                int k = kbase + lk + i;
                ra[i] = (aok && k < Kb) ? Ap[kbase + i] : 0.f;
            }
        }
    };
    auto loadB = [&](int kbase) {
        if (VEC == 2) {
            float4 v0, v1;
            if (bok) {
                v0 = *(const float4*)(Bp + kbase);
                v1 = *(const float4*)(Bp + kbase + 4);
            } else {
                v0 = make_float4(0.f, 0.f, 0.f, 0.f);
                v1 = v0;
            }
            rb[0] = v0.x; rb[1] = v0.y; rb[2] = v0.z; rb[3] = v0.w;
            rb[4] = v1.x; rb[5] = v1.y; rb[6] = v1.z; rb[7] = v1.w;
        } else {
            #pragma unroll
            for (int i = 0; i < 8; i++) {
                int k = kbase + lk + i;
                rb[i] = (bok && k < Kb) ? Bp[(size_t)(kbase + i) * ldbK] : 0.f;
            }
        }
    };

    loadA(0);
    loadB(0);

    int buf = 0;
    for (int k0 = 0; k0 < K; k0 += KSLAB) {
        float* AsH = smem + (buf * 4 + 0) * GTILE;
        float* AsL = smem + (buf * 4 + 1) * GTILE;
        float* BsH = smem + (buf * 4 + 2) * GTILE;
        float* BsL = smem + (buf * 4 + 3) * GTILE;

        // split + commit registers to current buffer
        #pragma unroll
        for (int i = 0; i < 8; i++) {
            int off = (lk + i) * GPAD + lr;
            uint32_t ah = f2tf32(ra[i]);
            float    al = ra[i] - __uint_as_float(ah);
            AsH[off] = __uint_as_float(ah);
            AsL[off] = __uint_as_float(f2tf32(al));
            uint32_t bh = f2tf32(rb[i]);
            float    bl = rb[i] - __uint_as_float(bh);
            BsH[off] = __uint_as_float(bh);
            BsL[off] = __uint_as_float(f2tf32(bl));
        }
        __syncthreads();

        // prefetch next slab
        int kn = k0 + KSLAB;
        if (kn < K) {
            loadA(kn);
            loadB(kn);
        }

        // compute: 2 k-steps of 8
        #pragma unroll
        for (int ks = 0; ks < 2; ks++) {
            const int kr0 = (ks * 8 + t) * GPAD;
            const int kr1 = (ks * 8 + t + 4) * GPAD;

            uint32_t aH[2][4], aL[2][4];
            #pragma unroll
            for (int mf = 0; mf < 2; mf++) {
                int m0 = wm + mf * 16 + g;
                aH[mf][0] = __float_as_uint(AsH[kr0 + m0]);
                aH[mf][1] = __float_as_uint(AsH[kr0 + m0 + 8]);
                aH[mf][2] = __float_as_uint(AsH[kr1 + m0]);
                aH[mf][3] = __float_as_uint(AsH[kr1 + m0 + 8]);
                aL[mf][0] = __float_as_uint(AsL[kr0 + m0]);
                aL[mf][1] = __float_as_uint(AsL[kr0 + m0 + 8]);
                aL[mf][2] = __float_as_uint(AsL[kr1 + m0]);
                aL[mf][3] = __float_as_uint(AsL[kr1 + m0 + 8]);
            }
            uint32_t bH[NF][2], bL[NF][2];
            #pragma unroll
            for (int nf = 0; nf < NF; nf++) {
                int n0 = wn + nf * 8 + g;
                bH[nf][0] = __float_as_uint(BsH[kr0 + n0]);
                bH[nf][1] = __float_as_uint(BsH[kr1 + n0]);
                bL[nf][0] = __float_as_uint(BsL[kr0 + n0]);
                bL[nf][1] = __float_as_uint(BsL[kr1 + n0]);
            }
            #pragma unroll
            for (int mf = 0; mf < 2; mf++)
                #pragma unroll
                for (int nf = 0; nf < NF; nf++) {
                    mma_tf32(acc[mf][nf], aH[mf], bH[nf]);
                    mma_tf32(acc[mf][nf], aH[mf], bL[nf]);
                    mma_tf32(acc[mf][nf], aL[mf], bH[nf]);
                }
        }
        buf ^= 1;
    }

    // epilogue: float2 stores (each thread owns cols {col, col+1}; N even ->
    // col < N implies col+1 < N; row bases and even cols are 8B-aligned).
    #pragma unroll
    for (int mf = 0; mf < 2; mf++) {
        #pragma unroll
        for (int half = 0; half < 2; half++) {
            int row = bm + wm + mf * 16 + g + half * 8;
            if (row >= M) continue;
            float* Cp = C + (size_t)row * ldc;
            const float* Up = (EPI == 2) ? (U + (size_t)row * ldc) : nullptr;
            #pragma unroll
            for (int nf = 0; nf < NF; nf++) {
                int col = bn + wn + nf * 8 + 2 * t;
                if (col < N) {
                    float v0 = acc[mf][nf][half * 2 + 0];
                    float v1 = acc[mf][nf][half * 2 + 1];
                    float2* dst = (float2*)&Cp[col];
                    if (EPI == 0) {
                        *dst = make_float2(v0 * scale, v1 * scale);
                    } else if (EPI == 1) {
                        float2 o = *dst;
                        *dst = make_float2(o.x + v0, o.y + v1);
                    } else {
                        float2 u = *(const float2*)&Up[col];
                        *dst = make_float2(v0 / (1.f + __expf(-v0)) * u.x,
                                           v1 / (1.f + __expf(-v1)) * u.y);
                    }
                }
            }
        }
    }
}

// ---------------------------------------------------------------------------
// Softmax over last axis (SEQ=1024), in place, full (no mask).
// Single global read + single global write: row cached in smem, float4 I/O.
// ---------------------------------------------------------------------------
__global__ __launch_bounds__(256)
void softmax_kernel(float* __restrict__ scores) {
    __shared__ float4 row[SEQ / 4];
    float4* p = (float4*)(scores + (size_t)blockIdx.x * SEQ);
    const int i = threadIdx.x;               // 256 threads = 256 float4 = 1024 floats

    float4 v = p[i];
    row[i] = v;
    float m = fmaxf(fmaxf(v.x, v.y), fmaxf(v.z, v.w));
    m = block_max(m);

    v = row[i];
    float4 e;
    e.x = __expf(v.x - m); e.y = __expf(v.y - m);
    e.z = __expf(v.z - m); e.w = __expf(v.w - m);
    row[i] = e;
    float s = (e.x + e.y) + (e.z + e.w);
    s = block_sum(s);

    float inv = 1.f / s;
    e = row[i];
    e.x *= inv; e.y *= inv; e.z *= inv; e.w *= inv;
    p[i] = e;
}

// ---------------------------------------------------------------------------
// Launch
// ---------------------------------------------------------------------------
extern "C" void kernel_launch(void* const* d_in, const int* in_sizes, int n_in,
                              void* d_out, int out_size) {
    const int*   ids    = (const int*)  d_in[0];
    const float* tok    = (const float*)d_in[1];
    const float* pos    = (const float*)d_in[2];
    const float* qkv_w  = (const float*)d_in[3];
    const float* o_w    = (const float*)d_in[4];
    const float* gate_w = (const float*)d_in[5];
    const float* up_w   = (const float*)d_in[6];
    const float* down_w = (const float*)d_in[7];
    const float* ln1w   = (const float*)d_in[8];
    const float* ln1b   = (const float*)d_in[9];
    const float* ln2w   = (const float*)d_in[10];
    const float* ln2b   = (const float*)d_in[11];
    const float* lnfw   = (const float*)d_in[12];
    const float* lnfb   = (const float*)d_in[13];
    const float* head_w = (const float*)d_in[14];
    float* out = (float*)d_out;

    float *h, *x, *qkvb, *sc, *ctx, *gt, *up;
    cudaGetSymbolAddress((void**)&h,    g_h);
    cudaGetSymbolAddress((void**)&x,    g_x);
    cudaGetSymbolAddress((void**)&qkvb, g_qkv);
    cudaGetSymbolAddress((void**)&sc,   g_scores);
    cudaGetSymbolAddress((void**)&ctx,  g_ctx);
    cudaGetSymbolAddress((void**)&gt,   g_gate);
    cudaGetSymbolAddress((void**)&up,   g_up);

    cudaFuncSetAttribute(gemm_mma<0,2,8>, cudaFuncAttributeMaxDynamicSharedMemorySize, (int)GSMEM_BYTES);
    cudaFuncSetAttribute(gemm_mma<2,2,8>, cudaFuncAttributeMaxDynamicSharedMemorySize, (int)GSMEM_BYTES);
    cudaFuncSetAttribute(gemm_mma<0,1,4>, cudaFuncAttributeMaxDynamicSharedMemorySize, (int)GSMEM_BYTES);
    cudaFuncSetAttribute(gemm_mma<1,2,4>, cudaFuncAttributeMaxDynamicSharedMemorySize, (int)GSMEM_BYTES);
    cudaFuncSetAttribute(gemm_mma<1,1,4>, cudaFuncAttributeMaxDynamicSharedMemorySize, (int)GSMEM_BYTES);

    embed_kernel<<<TOK, 256>>>(ids, tok, pos, h);

    const dim3 gQKV(QKV3 / 128, TOK / 128);                // 24 x 16
    const dim3 gO(HID / 64, TOK / 128);                    // 16 x 16  (NF=4)
    const dim3 gMLP((INTER + 127) / 128, TOK / 128);       // 22 x 16
    const dim3 gDN(HID / 64, TOK / 128);                   // 16 x 16  (NF=4)
    const dim3 gHead(VOCAB / 128, TOK / 128);              // 250 x 16
    const dim3 gScore(SEQ / 128, SEQ / 128, BATCH * NHEADS); // 8 x 8 x 32
    const dim3 gCtx(1, SEQ / 128, BATCH * NHEADS);         // 1 x 8 x 32 (NF=4: n-tile 64 = HDIM)

    const size_t Z0 = 0;
    const size_t sQb = (size_t)SEQ * QKV3;     // batch stride inside g_qkv
    const size_t sSb = (size_t)16 * SEQ * SEQ; // batch stride in scores (b)
    const size_t sSh = (size_t)SEQ * SEQ;      // head stride in scores (h)
    const size_t sCb = (size_t)SEQ * HID;      // batch stride in ctx

    for (int l = 0; l < NLAYERS; l++) {
        const float* lw_qkv  = qkv_w  + (size_t)l * QKV3 * HID;
        const float* lw_o    = o_w    + (size_t)l * HID * HID;
        const float* lw_gate = gate_w + (size_t)l * INTER * HID;
        const float* lw_up   = up_w   + (size_t)l * INTER * HID;
        const float* lw_down = down_w + (size_t)l * HID * INTER;

        // ---- attention block ----
        ln_kernel<<<TOK, 256>>>(h, ln1w + l * HID, ln1b + l * HID, x);
        gemm_mma<0,2,8><<<gQKV, 256, GSMEM_BYTES>>>(x, lw_qkv, qkvb, nullptr,
            TOK, QKV3, HID, HID, HID, HID, 1, QKV3, Z0, Z0, Z0, Z0, Z0, Z0, 1.f);

        // scores[bh] = scale * Q Kt
        gemm_mma<0,2,8><<<gScore, 256, GSMEM_BYTES>>>(qkvb, qkvb + HID, sc, nullptr,
            SEQ, SEQ, HDIM, HDIM, QKV3, QKV3, 1, SEQ,
            sQb, (size_t)HDIM, sQb, (size_t)HDIM, sSb, sSh, ATT_SCALE);

        softmax_kernel<<<BATCH * NHEADS * SEQ, 256>>>(sc);

        // ctx[bh] = P V : NF=4 (N=64), all warps productive; B strided -> VEC=1
        gemm_mma<0,1,4><<<gCtx, 256, GSMEM_BYTES>>>(sc, qkvb + 2 * HID, ctx, nullptr,
            SEQ, HDIM, SEQ, SEQ, SEQ, 1, QKV3, HID,
            sSb, sSh, sQb, (size_t)HDIM, sCb, (size_t)HDIM, 1.f);

        // O-proj: NF=4 -> 256 blocks, fills the chip
        gemm_mma<1,2,4><<<gO, 256, GSMEM_BYTES>>>(ctx, lw_o, h, nullptr,
            TOK, HID, HID, HID, HID, HID, 1, HID, Z0, Z0, Z0, Z0, Z0, Z0, 1.f);

        // ---- mlp block (activations stored with padded width INTERP) ----
        ln_kernel<<<TOK, 256>>>(h, ln2w + l * HID, ln2b + l * HID, x);
        gemm_mma<0,2,8><<<gMLP, 256, GSMEM_BYTES>>>(x, lw_up, up, nullptr,
            TOK, INTER, HID, HID, HID, HID, 1, INTERP, Z0, Z0, Z0, Z0, Z0, Z0, 1.f);
        gemm_mma<2,2,8><<<gMLP, 256, GSMEM_BYTES>>>(x, lw_gate, gt, up,
            TOK, INTER, HID, HID, HID, HID, 1, INTERP, Z0, Z0, Z0, Z0, Z0, Z0, 1.f);
        // down-proj: A padded to K=2736 (vector loads), B guard Kb=2730
        gemm_mma<1,1,4><<<gDN, 256, GSMEM_BYTES>>>(gt, lw_down, h, nullptr,
            TOK, HID, INTERP, INTER, INTERP, INTER, 1, HID, Z0, Z0, Z0, Z0, Z0, Z0, 1.f);
    }

    ln_kernel<<<TOK, 256>>>(h, lnfw, lnfb, x);
    gemm_mma<0,2,8><<<gHead, 256, GSMEM_BYTES>>>(x, head_w, out, nullptr,
        TOK, VOCAB, HID, HID, HID, HID, 1, VOCAB, Z0, Z0, Z0, Z0, Z0, Z0, 1.f);
}

// round 16
// speedup vs baseline: 1.6452x; 1.6452x over previous
#include <cuda_runtime.h>
#include <cuda_bf16.h>
#include <math.h>
#include <stdint.h>

// Problem constants
#define SEQ     1024
#define BATCH   2
#define TOK     (SEQ*BATCH)   // 2048 tokens
#define HID     1024
#define NHEADS  16
#define HDIM    64
#define INTER   2730
#define INTERP  2736          // INTER padded to %16 (=171*16) for vector loads
#define NLAYERS 6
#define VOCAB   32000
#define QKV3    (3*HID)       // 3072
#define LN_EPS  1e-5f
#define ATT_SCALE 0.125f      // 1/sqrt(64)

// MMA GEMM smem geometry: k-slab 16, row pad 136 floats.
// Mainloop frag reads: bank = (8*t + g + c) % 32 -> exact 0..31 cover, conflict-free.
#define KSLAB 16
#define GPAD  136
#define GTILE (KSLAB*GPAD)                       // floats per array per stage
#define GSMEM_BYTES (2*4*GTILE*sizeof(float))    // 2 stages x {AsH,AsL,BsH,BsL} = 68KB

// ---------------------------------------------------------------------------
// Scratch (static __device__ globals: allocation-guard safe, zero-initialized
// at module load — the INTERP padding columns are never written and stay 0).
// ---------------------------------------------------------------------------
__device__ float g_h[TOK*HID];
__device__ float g_x[TOK*HID];
__device__ float g_qkv[TOK*QKV3];
__device__ float g_scores[(size_t)BATCH*NHEADS*SEQ*SEQ];
__device__ float g_ctx[TOK*HID];
__device__ float g_gate[(size_t)TOK*INTERP];
__device__ float g_up[(size_t)TOK*INTERP];

// ---------------------------------------------------------------------------
// Block reductions
// ---------------------------------------------------------------------------
__device__ __forceinline__ float block_sum(float v) {
    __shared__ float red[32];
    int lane = threadIdx.x & 31, w = threadIdx.x >> 5;
    __syncthreads();
    #pragma unroll
    for (int o = 16; o > 0; o >>= 1) v += __shfl_down_sync(0xffffffffu, v, o);
    if (lane == 0) red[w] = v;
    __syncthreads();
    int nw = blockDim.x >> 5;
    float r = (threadIdx.x < nw) ? red[threadIdx.x] : 0.f;
    if (w == 0) {
        #pragma unroll
        for (int o = 16; o > 0; o >>= 1) r += __shfl_down_sync(0xffffffffu, r, o);
        if (lane == 0) red[0] = r;
    }
    __syncthreads();
    return red[0];
}

__device__ __forceinline__ float block_max(float v) {
    __shared__ float red[32];
    int lane = threadIdx.x & 31, w = threadIdx.x >> 5;
    __syncthreads();
    #pragma unroll
    for (int o = 16; o > 0; o >>= 1) v = fmaxf(v, __shfl_down_sync(0xffffffffu, v, o));
    if (lane == 0) red[w] = v;
    __syncthreads();
    int nw = blockDim.x >> 5;
    float r = (threadIdx.x < nw) ? red[threadIdx.x] : -1e30f;
    if (w == 0) {
        #pragma unroll
        for (int o = 16; o > 0; o >>= 1) r = fmaxf(r, __shfl_down_sync(0xffffffffu, r, o));
        if (lane == 0) red[0] = r;
    }
    __syncthreads();
    return red[0];
}

// ---------------------------------------------------------------------------
// tf32 helpers
// ---------------------------------------------------------------------------
__device__ __forceinline__ uint32_t f2tf32(float x) {
    uint32_t r;
    asm("cvt.rna.tf32.f32 %0, %1;" : "=r"(r) : "f"(x));
    return r;
}

__device__ __forceinline__ void mma_tf32(float c[4], const uint32_t a[4], const uint32_t b[2]) {
    asm volatile(
        "mma.sync.aligned.m16n8k8.row.col.f32.tf32.tf32.f32 "
        "{%0,%1,%2,%3}, {%4,%5,%6,%7}, {%8,%9}, {%0,%1,%2,%3};"
        : "+f"(c[0]), "+f"(c[1]), "+f"(c[2]), "+f"(c[3])
        : "r"(a[0]), "r"(a[1]), "r"(a[2]), "r"(a[3]), "r"(b[0]), "r"(b[1]));
}

// ---------------------------------------------------------------------------
// Embedding
// ---------------------------------------------------------------------------
__global__ void embed_kernel(const int* __restrict__ ids, const float* __restrict__ tok,
                             const float* __restrict__ pos, float* __restrict__ h) {
    int t = blockIdx.x;
    int s = t % SEQ;
    int id = ids[t];
    const float* te = tok + (size_t)id * HID;
    const float* pe = pos + (size_t)s * HID;
    float* hp = h + (size_t)t * HID;
    for (int i = threadIdx.x; i < HID; i += blockDim.x) hp[i] = te[i] + pe[i];
}

// ---------------------------------------------------------------------------
// LayerNorm
// ---------------------------------------------------------------------------
__global__ void ln_kernel(const float* __restrict__ in, const float* __restrict__ w,
                          const float* __restrict__ bb, float* __restrict__ out) {
    __shared__ float row[HID];
    int t = blockIdx.x;
    const float* xp = in + (size_t)t * HID;
    float s = 0.f;
    for (int i = threadIdx.x; i < HID; i += blockDim.x) { float v = xp[i]; row[i] = v; s += v; }
    s = block_sum(s);
    float mu = s * (1.f / HID);
    float s2 = 0.f;
    for (int i = threadIdx.x; i < HID; i += blockDim.x) { float d = row[i] - mu; s2 += d * d; }
    s2 = block_sum(s2);
    float rstd = rsqrtf(s2 * (1.f / HID) + LN_EPS);
    float* op = out + (size_t)t * HID;
    for (int i = threadIdx.x; i < HID; i += blockDim.x)
        op[i] = (row[i] - mu) * rstd * w[i] + bb[i];
}

// ---------------------------------------------------------------------------
// Unified tensor-core GEMM (3xTF32):
//   C[m,n] = scale * sum_{k<Kb} A[m*lda + k] * B[n*ldbN + k*ldbK]  (+ EPI)
// K = k-loop extent (%KSLAB for VEC>=1 A); Kb = real reduction depth used for
// scalar-path guards. When K > Kb (padded-A case) A's padding MUST be zeros.
// Batched via blockIdx.z: operand offsets (z>>4)*so + (z&15)*si.
// Block tile 128 x (16*NF), 256 threads = 8 warps (4m x 2n),
// warp tile 32 x (8*NF). NF=8 -> 128-wide tile, NF=4 -> 64-wide tile.
// mma.m16n8k8.tf32, hi/lo split at smem-store time, double-buffered.
//
// __launch_bounds__(256, 2): round-10 ncu showed regs=130 -> 1 CTA/SM
// (occ 12.1%, tensor 39.7%). Forcing the 128-reg budget + keeping B-frags
// live per-nf (not all 8 at once) gets 2 CTAs/SM.
//
// EPI: 0 = C = scale*acc, 1 = C += acc, 2 = C = silu(acc) * U
// VEC: 0 = scalar loads, 1 = float4 A only (B scalar), 2 = float4 A and B.
//      VEC>=1 requires K%16==0 and 16B-aligned A rows; VEC==2 additionally
//      ldbK==1, 16B-aligned B rows, and K==Kb. N must be even.
//
// Fragment layouts (lane = g*4+t):
//   A: a0=(g,t) a1=(g+8,t) a2=(g,t+4) a3=(g+8,t+4)   [m, k]
//   B: b0=(t,g) b1=(t+4,g)                            [k, n]
//   C: c0=(g,2t) c1=(g,2t+1) c2=(g+8,2t) c3=(g+8,2t+1)
// ---------------------------------------------------------------------------
template<int EPI, int VEC, int NF>
__global__ __launch_bounds__(256, 2)
void gemm_mma(const float* __restrict__ A, const float* __restrict__ B,
              float* __restrict__ C, const float* __restrict__ U,
              int M, int N, int K, int Kb,
              int lda, int ldbN, int ldbK, int ldc,
              size_t sAo, size_t sAi, size_t sBo, size_t sBi,
              size_t sCo, size_t sCi, float scale) {
    extern __shared__ float smem[];
    const unsigned z = blockIdx.z;
    A += (size_t)(z >> 4) * sAo + (size_t)(z & 15) * sAi;
    B += (size_t)(z >> 4) * sBo + (size_t)(z & 15) * sBi;
    C += (size_t)(z >> 4) * sCo + (size_t)(z & 15) * sCi;

    const int bm = blockIdx.y * 128, bn = blockIdx.x * (16 * NF);
    const int tid = threadIdx.x;
    const int wid = tid >> 5, lane = tid & 31;
    const int g = lane >> 2, t = lane & 3;
    const int wm = (wid >> 1) * 32;         // warp row offset (0,32,64,96)
    const int wn = (wid & 1) * (8 * NF);    // warp col offset

    // loaders: 256 threads cover 128 rows x 16 k
    const int lr = tid >> 1;            // 0..127
    const int lk = (tid & 1) * 8;       // 0 or 8

    float acc[2][NF][4];
    #pragma unroll
    for (int mf = 0; mf < 2; mf++)
        #pragma unroll
        for (int nf = 0; nf < NF; nf++)
            #pragma unroll
            for (int r = 0; r < 4; r++) acc[mf][nf][r] = 0.f;

    const int arow = bm + lr;
    const int brow = bn + lr;
    const bool aok = arow < M, bok = brow < N;
    const float* Ap = A + (size_t)arow * lda + lk;              // A k-stride always 1
    const float* Bp = B + (size_t)brow * ldbN + (size_t)lk * ldbK;

    float ra[8], rb[8];

    // ---- load helpers (compile-time dispatch) ----
    auto loadA = [&](int kbase) {
        if (VEC >= 1) {
            float4 v0, v1;
            if (aok) {
                v0 = *(const float4*)(Ap + kbase);
                v1 = *(const float4*)(Ap + kbase + 4);
            } else {
                v0 = make_float4(0.f, 0.f, 0.f, 0.f);
                v1 = v0;
            }
            ra[0] = v0.x; ra[1] = v0.y; ra[2] = v0.z; ra[3] = v0.w;
            ra[4] = v1.x; ra[5] = v1.y; ra[6] = v1.z; ra[7] = v1.w;
        } else {
            #pragma unroll
            for (int i = 0; i < 8; i++) {
                int k = kbase + lk + i;
                ra[i] = (aok && k < Kb) ? Ap[kbase + i] : 0.f;
            }
        }
    };
    auto loadB = [&](int kbase) {
        if (VEC == 2) {
            float4 v0, v1;
            if (bok) {
                v0 = *(const float4*)(Bp + kbase);
                v1 = *(const float4*)(Bp + kbase + 4);
            } else {
                v0 = make_float4(0.f, 0.f, 0.f, 0.f);
                v1 = v0;
            }
            rb[0] = v0.x; rb[1] = v0.y; rb[2] = v0.z; rb[3] = v0.w;
            rb[4] = v1.x; rb[5] = v1.y; rb[6] = v1.z; rb[7] = v1.w;
        } else {
            #pragma unroll
            for (int i = 0; i < 8; i++) {
                int k = kbase + lk + i;
                rb[i] = (bok && k < Kb) ? Bp[(size_t)(kbase + i) * ldbK] : 0.f;
            }
        }
    };

    loadA(0);
    loadB(0);

    int buf = 0;
    for (int k0 = 0; k0 < K; k0 += KSLAB) {
        float* AsH = smem + (buf * 4 + 0) * GTILE;
        float* AsL = smem + (buf * 4 + 1) * GTILE;
        float* BsH = smem + (buf * 4 + 2) * GTILE;
        float* BsL = smem + (buf * 4 + 3) * GTILE;

        // split + commit registers to current buffer
        #pragma unroll
        for (int i = 0; i < 8; i++) {
            int off = (lk + i) * GPAD + lr;
            uint32_t ah = f2tf32(ra[i]);
            float    al = ra[i] - __uint_as_float(ah);
            AsH[off] = __uint_as_float(ah);
            AsL[off] = __uint_as_float(f2tf32(al));
            uint32_t bh = f2tf32(rb[i]);
            float    bl = rb[i] - __uint_as_float(bh);
            BsH[off] = __uint_as_float(bh);
            BsL[off] = __uint_as_float(f2tf32(bl));
        }
        __syncthreads();

        // prefetch next slab
        int kn = k0 + KSLAB;
        if (kn < K) {
            loadA(kn);
            loadB(kn);
        }

        // compute: 2 k-steps of 8
        #pragma unroll
        for (int ks = 0; ks < 2; ks++) {
            const int kr0 = (ks * 8 + t) * GPAD;
            const int kr1 = (ks * 8 + t + 4) * GPAD;

            uint32_t aH[2][4], aL[2][4];
            #pragma unroll
            for (int mf = 0; mf < 2; mf++) {
                int m0 = wm + mf * 16 + g;
                aH[mf][0] = __float_as_uint(AsH[kr0 + m0]);
                aH[mf][1] = __float_as_uint(AsH[kr0 + m0 + 8]);
                aH[mf][2] = __float_as_uint(AsH[kr1 + m0]);
                aH[mf][3] = __float_as_uint(AsH[kr1 + m0 + 8]);
                aL[mf][0] = __float_as_uint(AsL[kr0 + m0]);
                aL[mf][1] = __float_as_uint(AsL[kr0 + m0 + 8]);
                aL[mf][2] = __float_as_uint(AsL[kr1 + m0]);
                aL[mf][3] = __float_as_uint(AsL[kr1 + m0 + 8]);
            }
            // B-frags loaded per-nf (only 4 b-regs live at a time; each frag
            // still read exactly once) — keeps total regs under the 128 budget.
            #pragma unroll
            for (int nf = 0; nf < NF; nf++) {
                int n0 = wn + nf * 8 + g;
                uint32_t bH[2], bL[2];
                bH[0] = __float_as_uint(BsH[kr0 + n0]);
                bH[1] = __float_as_uint(BsH[kr1 + n0]);
                bL[0] = __float_as_uint(BsL[kr0 + n0]);
                bL[1] = __float_as_uint(BsL[kr1 + n0]);
                #pragma unroll
                for (int mf = 0; mf < 2; mf++) {
                    mma_tf32(acc[mf][nf], aH[mf], bH);
                    mma_tf32(acc[mf][nf], aH[mf], bL);
                    mma_tf32(acc[mf][nf], aL[mf], bH);
                }
            }
        }
        buf ^= 1;
    }

    // epilogue: float2 stores (each thread owns cols {col, col+1}; N even ->
    // col < N implies col+1 < N; row bases and even cols are 8B-aligned).
    #pragma unroll
    for (int mf = 0; mf < 2; mf++) {
        #pragma unroll
        for (int half = 0; half < 2; half++) {
            int row = bm + wm + mf * 16 + g + half * 8;
            if (row >= M) continue;
            float* Cp = C + (size_t)row * ldc;
            const float* Up = (EPI == 2) ? (U + (size_t)row * ldc) : nullptr;
            #pragma unroll
            for (int nf = 0; nf < NF; nf++) {
                int col = bn + wn + nf * 8 + 2 * t;
                if (col < N) {
                    float v0 = acc[mf][nf][half * 2 + 0];
                    float v1 = acc[mf][nf][half * 2 + 1];
                    float2* dst = (float2*)&Cp[col];
                    if (EPI == 0) {
                        *dst = make_float2(v0 * scale, v1 * scale);
                    } else if (EPI == 1) {
                        float2 o = *dst;
                        *dst = make_float2(o.x + v0, o.y + v1);
                    } else {
                        float2 u = *(const float2*)&Up[col];
                        *dst = make_float2(v0 / (1.f + __expf(-v0)) * u.x,
                                           v1 / (1.f + __expf(-v1)) * u.y);
                    }
                }
            }
        }
    }
}

// ---------------------------------------------------------------------------
// Softmax over last axis (SEQ=1024), in place, full (no mask).
// Single global read + single global write: row cached in smem, float4 I/O.
// ---------------------------------------------------------------------------
__global__ __launch_bounds__(256)
void softmax_kernel(float* __restrict__ scores) {
    __shared__ float4 row[SEQ / 4];
    float4* p = (float4*)(scores + (size_t)blockIdx.x * SEQ);
    const int i = threadIdx.x;               // 256 threads = 256 float4 = 1024 floats

    float4 v = p[i];
    row[i] = v;
    float m = fmaxf(fmaxf(v.x, v.y), fmaxf(v.z, v.w));
    m = block_max(m);

    v = row[i];
    float4 e;
    e.x = __expf(v.x - m); e.y = __expf(v.y - m);
    e.z = __expf(v.z - m); e.w = __expf(v.w - m);
    row[i] = e;
    float s = (e.x + e.y) + (e.z + e.w);
    s = block_sum(s);

    float inv = 1.f / s;
    e = row[i];
    e.x *= inv; e.y *= inv; e.z *= inv; e.w *= inv;
    p[i] = e;
}

// ---------------------------------------------------------------------------
// Launch
// ---------------------------------------------------------------------------
extern "C" void kernel_launch(void* const* d_in, const int* in_sizes, int n_in,
                              void* d_out, int out_size) {
    const int*   ids    = (const int*)  d_in[0];
    const float* tok    = (const float*)d_in[1];
    const float* pos    = (const float*)d_in[2];
    const float* qkv_w  = (const float*)d_in[3];
    const float* o_w    = (const float*)d_in[4];
    const float* gate_w = (const float*)d_in[5];
    const float* up_w   = (const float*)d_in[6];
    const float* down_w = (const float*)d_in[7];
    const float* ln1w   = (const float*)d_in[8];
    const float* ln1b   = (const float*)d_in[9];
    const float* ln2w   = (const float*)d_in[10];
    const float* ln2b   = (const float*)d_in[11];
    const float* lnfw   = (const float*)d_in[12];
    const float* lnfb   = (const float*)d_in[13];
    const float* head_w = (const float*)d_in[14];
    float* out = (float*)d_out;

    float *h, *x, *qkvb, *sc, *ctx, *gt, *up;
    cudaGetSymbolAddress((void**)&h,    g_h);
    cudaGetSymbolAddress((void**)&x,    g_x);
    cudaGetSymbolAddress((void**)&qkvb, g_qkv);
    cudaGetSymbolAddress((void**)&sc,   g_scores);
    cudaGetSymbolAddress((void**)&ctx,  g_ctx);
    cudaGetSymbolAddress((void**)&gt,   g_gate);
    cudaGetSymbolAddress((void**)&up,   g_up);

    cudaFuncSetAttribute(gemm_mma<0,2,8>, cudaFuncAttributeMaxDynamicSharedMemorySize, (int)GSMEM_BYTES);
    cudaFuncSetAttribute(gemm_mma<2,2,8>, cudaFuncAttributeMaxDynamicSharedMemorySize, (int)GSMEM_BYTES);
    cudaFuncSetAttribute(gemm_mma<0,1,4>, cudaFuncAttributeMaxDynamicSharedMemorySize, (int)GSMEM_BYTES);
    cudaFuncSetAttribute(gemm_mma<1,2,4>, cudaFuncAttributeMaxDynamicSharedMemorySize, (int)GSMEM_BYTES);
    cudaFuncSetAttribute(gemm_mma<1,1,4>, cudaFuncAttributeMaxDynamicSharedMemorySize, (int)GSMEM_BYTES);

    embed_kernel<<<TOK, 256>>>(ids, tok, pos, h);

    const dim3 gQKV(QKV3 / 128, TOK / 128);                // 24 x 16
    const dim3 gO(HID / 64, TOK / 128);                    // 16 x 16  (NF=4)
    const dim3 gMLP((INTER + 127) / 128, TOK / 128);       // 22 x 16
    const dim3 gDN(HID / 64, TOK / 128);                   // 16 x 16  (NF=4)
    const dim3 gHead(VOCAB / 128, TOK / 128);              // 250 x 16
    const dim3 gScore(SEQ / 128, SEQ / 128, BATCH * NHEADS); // 8 x 8 x 32
    const dim3 gCtx(1, SEQ / 128, BATCH * NHEADS);         // 1 x 8 x 32 (NF=4: n-tile 64 = HDIM)

    const size_t Z0 = 0;
    const size_t sQb = (size_t)SEQ * QKV3;     // batch stride inside g_qkv
    const size_t sSb = (size_t)16 * SEQ * SEQ; // batch stride in scores (b)
    const size_t sSh = (size_t)SEQ * SEQ;      // head stride in scores (h)
    const size_t sCb = (size_t)SEQ * HID;      // batch stride in ctx

    for (int l = 0; l < NLAYERS; l++) {
        const float* lw_qkv  = qkv_w  + (size_t)l * QKV3 * HID;
        const float* lw_o    = o_w    + (size_t)l * HID * HID;
        const float* lw_gate = gate_w + (size_t)l * INTER * HID;
        const float* lw_up   = up_w   + (size_t)l * INTER * HID;
        const float* lw_down = down_w + (size_t)l * HID * INTER;

        // ---- attention block ----
        ln_kernel<<<TOK, 256>>>(h, ln1w + l * HID, ln1b + l * HID, x);
        gemm_mma<0,2,8><<<gQKV, 256, GSMEM_BYTES>>>(x, lw_qkv, qkvb, nullptr,
            TOK, QKV3, HID, HID, HID, HID, 1, QKV3, Z0, Z0, Z0, Z0, Z0, Z0, 1.f);

        // scores[bh] = scale * Q Kt
        gemm_mma<0,2,8><<<gScore, 256, GSMEM_BYTES>>>(qkvb, qkvb + HID, sc, nullptr,
            SEQ, SEQ, HDIM, HDIM, QKV3, QKV3, 1, SEQ,
            sQb, (size_t)HDIM, sQb, (size_t)HDIM, sSb, sSh, ATT_SCALE);

        softmax_kernel<<<BATCH * NHEADS * SEQ, 256>>>(sc);

        // ctx[bh] = P V : NF=4 (N=64), all warps productive; B strided -> VEC=1
        gemm_mma<0,1,4><<<gCtx, 256, GSMEM_BYTES>>>(sc, qkvb + 2 * HID, ctx, nullptr,
            SEQ, HDIM, SEQ, SEQ, SEQ, 1, QKV3, HID,
            sSb, sSh, sQb, (size_t)HDIM, sCb, (size_t)HDIM, 1.f);

        // O-proj: NF=4 -> 256 blocks, fills the chip
        gemm_mma<1,2,4><<<gO, 256, GSMEM_BYTES>>>(ctx, lw_o, h, nullptr,
            TOK, HID, HID, HID, HID, HID, 1, HID, Z0, Z0, Z0, Z0, Z0, Z0, 1.f);

        // ---- mlp block (activations stored with padded width INTERP) ----
        ln_kernel<<<TOK, 256>>>(h, ln2w + l * HID, ln2b + l * HID, x);
        gemm_mma<0,2,8><<<gMLP, 256, GSMEM_BYTES>>>(x, lw_up, up, nullptr,
            TOK, INTER, HID, HID, HID, HID, 1, INTERP, Z0, Z0, Z0, Z0, Z0, Z0, 1.f);
        gemm_mma<2,2,8><<<gMLP, 256, GSMEM_BYTES>>>(x, lw_gate, gt, up,
            TOK, INTER, HID, HID, HID, HID, 1, INTERP, Z0, Z0, Z0, Z0, Z0, Z0, 1.f);
        // down-proj: A padded to K=2736 (vector loads), B guard Kb=2730
        gemm_mma<1,1,4><<<gDN, 256, GSMEM_BYTES>>>(gt, lw_down, h, nullptr,
            TOK, HID, INTERP, INTER, INTERP, INTER, 1, HID, Z0, Z0, Z0, Z0, Z0, Z0, 1.f);
    }

    ln_kernel<<<TOK, 256>>>(h, lnfw, lnfb, x);
    gemm_mma<0,2,8><<<gHead, 256, GSMEM_BYTES>>>(x, head_w, out, nullptr,
        TOK, VOCAB, HID, HID, HID, HID, 1, VOCAB, Z0, Z0, Z0, Z0, Z0, Z0, 1.f);
}